// round 4
// baseline (speedup 1.0000x reference)
#include <cuda_runtime.h>
#include <cuda_bf16.h>
#include <math.h>

// z is (Kn=4, M=128, D=64, T=256)
#define Tn    256
#define NMID  254
#define ND    64
#define NKM   512
#define BW    9
#define BWP   12           // padded band stride (3x float4)
#define NPAD  272
#define NSTEP 261          // 29*9 recursion steps (padded past NMID)
#define JUMPJ 234          // 26*9: resume point after Toeplitz skip
#define EPSv  1e-5f

__device__ float g_Lb[ND][NMID * BWP];  // banded L, padded: g_Lb[d][i*12+c] = L[i][i-c], c<9
__device__ float g_A0[ND][NMID];
__device__ float g_A1[ND][NMID];
__device__ float g_pld[ND];

// ---------------------------------------------------------------------------
// Setup: one warp per d. Banded register-window Cholesky with Toeplitz
// convergence jump (column-wise stencil fill preserves exact recursion
// semantics). gc[] hoisted to smem (9 expf instead of per-element expf).
// ---------------------------------------------------------------------------
__global__ __launch_bounds__(32) void setup_kernel(const float* __restrict__ log_tau) {
    const int d = blockIdx.x;
    const int lane = threadIdx.x;

    __shared__ float Kp0[NMID], Kp1[NMID], A0s[NMID], A1s[NMID];
    __shared__ float Sb[NPAD][BW];
    __shared__ float stc[BW];
    __shared__ float gcs[BW];

    const float tau = expf(log_tau[d]);
    const float h = 1.0f / (2.0f * tau * tau);
    const float r255 = expf(-h * 255.0f * 255.0f);
    const float idet = 1.0f / (1.0f - r255 * r255);

    if (lane < BW) gcs[lane] = expf(-h * (float)(lane * lane));

    for (int i = lane; i < NMID; i += 32) {
        float x0 = (float)(i + 1);
        float x1 = (float)(254 - i);
        float k0 = expf(-h * x0 * x0);
        float k1 = expf(-h * x1 * x1);
        Kp0[i] = k0; Kp1[i] = k1;
        float a0 = idet * (k0 - r255 * k1);
        float a1 = idet * (k1 - r255 * k0);
        A0s[i] = a0; A1s[i] = a1;
        g_A0[d][i] = a0; g_A1[d][i] = a1;
    }
    __syncwarp();

    for (int idx = lane; idx < NPAD * BW; idx += 32) {
        int i = idx / BW;
        int c = idx - i * BW;
        float v = 0.0f;
        if (i < NMID) {
            if (c <= i) {
                v = gcs[c] - A0s[i] * Kp0[i - c] - A1s[i] * Kp1[i - c];
                if (c == 0) v += EPSv;
            }
        } else {
            v = (c == 0) ? 1.0f : 0.0f;
        }
        Sb[i][c] = v;
    }
    __syncwarp();

    float W[9][9];
#pragma unroll
    for (int s = 0; s < 9; ++s)
#pragma unroll
        for (int c = 0; c < 9; ++c)
            W[s][c] = Sb[s][c];

    float prod = 1.0f;
    float ld_skip = 0.0f;
    float lprev[9];
#pragma unroll
    for (int c = 0; c < 9; ++c) lprev[c] = -1.0f;
    bool conv = false, jumped = false;
    int j = 0;
    float* __restrict__ Ld = g_Lb[d];

    while (j < NSTEP) {
        // block boundary (j % 9 == 0): jump if window is stationary
        if (conv && !jumped && j <= 225) {
#pragma unroll
            for (int c = 0; c < 9; ++c)
                if (lane == c) stc[c] = lprev[c];
            __syncwarp();
            const int skip = JUMPJ - j;
            // column-wise fill: replicate exactly what the recursion writes
            for (int idx = lane; idx < skip * BW; idx += 32) {
                int jc = j + idx / BW;
                int c  = idx - (idx / BW) * BW;
                int r  = jc + c;
                if (r < NMID)
                    Ld[r * BWP + c] = stc[c];
            }
            __syncwarp();
            ld_skip = (float)skip * logf(lprev[0]);
            j = JUMPJ;
            jumped = true;
        }
#pragma unroll
        for (int s = 0; s < 9; ++s) {
            float x = W[s][0];
            float inv = rsqrtf(x);
            float dg = x * inv;

            float l[9];
            l[0] = dg;
#pragma unroll
            for (int c = 1; c < 9; ++c)
                l[c] = W[(s + c) % 9][c] * inv;

            bool eq = true;
#pragma unroll
            for (int c = 0; c < 9; ++c) eq = eq && (l[c] == lprev[c]);
            if (eq && j >= 12) conv = true;
#pragma unroll
            for (int c = 0; c < 9; ++c) lprev[c] = l[c];

#pragma unroll
            for (int c = 0; c < 9; ++c)
                if (lane == c && j + c < NMID)
                    Ld[(j + c) * BWP + c] = l[c];

#pragma unroll
            for (int r1 = 1; r1 < 9; ++r1)
#pragma unroll
                for (int r2 = 1; r2 <= r1; ++r2)
                    W[(s + r1) % 9][r1 - r2] -= l[r1] * l[r2];

            {
                const float* src = Sb[j + 9];
#pragma unroll
                for (int c = 0; c < 9; ++c)
                    W[s][c] = src[c];
            }

            if (j < NMID) prod *= dg;
            ++j;
        }
    }

    if (lane == 0) g_pld[d] = logf(prod) + ld_skip;
}

// ---------------------------------------------------------------------------
// Apply: z_out = [z0 | A z_EP + L z_mid | zE]. Thread owns 4 consecutive t
// (float4-aligned); 4 L-rows + a0/a1 in registers (loaded as float4 from the
// padded band). Rows streamed with depth-1 software pipeline (next row's
// 3x LDG.128 + 2 LDG.32 issued before computing current row) -> MLP ~10.
// Grid (64,16): 8 rows/thread, 1024 blocks.
// ---------------------------------------------------------------------------
__global__ __launch_bounds__(256, 3) void apply_kernel(const float* __restrict__ z,
                                                       const float* __restrict__ sldj,
                                                       float* __restrict__ out,
                                                       int osize) {
    const int d = blockIdx.x;
    const int chunk = blockIdx.y;          // 0..15, 32 km-rows each
    const int tid = threadIdx.x;
    const int tg = tid & 63;               // outputs t0..t0+3
    const int rs = tid >> 6;               // row slot 0..3
    const int t0 = tg << 2;

    if (d == 0 && chunk == 0 && tid == 0) {
        float s = sldj[0];
        for (int dd = 0; dd < ND; ++dd) s += g_pld[dd];
        out[osize - 1] = s;
    }

    // Per-thread L rows i = t0+u-1 (padded float4 loads)
    float L[4][9];
    float a0[4], a1[4];
#pragma unroll
    for (int u = 0; u < 4; ++u) {
        int i = t0 + u - 1;
        bool valid = (i >= 0) && (i < NMID);
        if (valid) {
            const float4* p = reinterpret_cast<const float4*>(&g_Lb[d][i * BWP]);
            float4 f0 = p[0], f1 = p[1], f2 = p[2];
            L[u][0] = f0.x; L[u][1] = f0.y; L[u][2] = f0.z; L[u][3] = f0.w;
            L[u][4] = f1.x; L[u][5] = f1.y; L[u][6] = f1.z; L[u][7] = f1.w;
            L[u][8] = f2.x;
            a0[u] = g_A0[d][i];
            a1[u] = g_A1[d][i];
        } else {
#pragma unroll
            for (int c = 0; c < 9; ++c) L[u][c] = 0.0f;
            a0[u] = 0.0f; a1[u] = 0.0f;
        }
    }

    const int base_km = chunk * 32 + rs;               // rows: base_km + 4*iter
    const float* __restrict__ zr = z + (size_t)(base_km * ND + d) * Tn;
    float* __restrict__ orow = out + (size_t)(base_km * ND + d) * Tn + t0;
    const size_t zstep = (size_t)4 * ND * Tn;          // advance 4 km-rows

    const bool has1 = (tg >= 1);
    const bool has0 = (tg >= 2);

    // prologue: load row 0
    float4 q2 = *reinterpret_cast<const float4*>(zr + t0);
    float4 q1 = make_float4(0.f, 0.f, 0.f, 0.f);
    float4 q0 = make_float4(0.f, 0.f, 0.f, 0.f);
    if (has1) q1 = *reinterpret_cast<const float4*>(zr + t0 - 4);
    if (has0) q0 = *reinterpret_cast<const float4*>(zr + t0 - 8);
    float z0 = zr[0];
    float zE = zr[255];

#pragma unroll
    for (int iter = 0; iter < 8; ++iter) {
        // prefetch next row
        float4 n2 = make_float4(0.f, 0.f, 0.f, 0.f);
        float4 n1 = make_float4(0.f, 0.f, 0.f, 0.f);
        float4 n0 = make_float4(0.f, 0.f, 0.f, 0.f);
        float nz0 = 0.f, nzE = 0.f;
        if (iter < 7) {
            const float* zn = zr + zstep;
            n2 = *reinterpret_cast<const float4*>(zn + t0);
            if (has1) n1 = *reinterpret_cast<const float4*>(zn + t0 - 4);
            if (has0) n0 = *reinterpret_cast<const float4*>(zn + t0 - 8);
            nz0 = zn[0];
            nzE = zn[255];
        }

        // compute current row
        float w[12];
        w[0] = q0.x; w[1] = q0.y; w[2] = q0.z; w[3] = q0.w;
        w[4] = q1.x; w[5] = q1.y; w[6] = q1.z; w[7] = q1.w;
        w[8] = q2.x; w[9] = q2.y; w[10] = q2.z; w[11] = q2.w;

        float v[4];
#pragma unroll
        for (int u = 0; u < 4; ++u) {
            float acc = a0[u] * z0 + a1[u] * zE;
#pragma unroll
            for (int c = 0; c < 9; ++c)
                acc += L[u][c] * w[u - c + 8];
            v[u] = acc;
        }
        if (tg == 0)  v[0] = z0;
        if (tg == 63) v[3] = zE;

        *reinterpret_cast<float4*>(orow) = make_float4(v[0], v[1], v[2], v[3]);

        // rotate
        q2 = n2; q1 = n1; q0 = n0; z0 = nz0; zE = nzE;
        zr += zstep;
        orow += zstep;
    }
}

extern "C" void kernel_launch(void* const* d_in, const int* in_sizes, int n_in,
                              void* d_out, int out_size) {
    const float* z = (const float*)d_in[0];
    const float* sldj = (const float*)d_in[1];
    const float* log_tau = (const float*)d_in[2];
    float* out = (float*)d_out;

    setup_kernel<<<ND, 32>>>(log_tau);
    apply_kernel<<<dim3(ND, 16), 256>>>(z, sldj, out, out_size);
}

// round 5
// speedup vs baseline: 1.1087x; 1.1087x over previous
#include <cuda_runtime.h>
#include <cuda_bf16.h>
#include <math.h>

// z is (Kn=4, M=128, D=64, T=256)
#define Tn    256
#define NMID  254
#define ND    64
#define BW    9
#define BWP   12           // padded band stride (3x float4)
#define NPAD  272
#define NSTEP 261
#define JUMPJ 234          // 26*9: resume point after Toeplitz skip
#define EPSv  1e-5f

#define RSTRIDE 264        // smem row stride in floats: 8 pad + 256
#define NROWBUF 16         // 4 stages x 4 rows

__device__ float g_Lb[ND][NMID * BWP];  // banded L, padded: g_Lb[d][i*12+c] = L[i][i-c]
__device__ float g_A0[ND][NMID];
__device__ float g_A1[ND][NMID];
__device__ float g_pld[ND];

// ---------------------------------------------------------------------------
// Setup: one warp per d. Banded register-window Cholesky with Toeplitz
// convergence jump (column-wise stencil fill = exact recursion semantics).
// ---------------------------------------------------------------------------
__global__ __launch_bounds__(32) void setup_kernel(const float* __restrict__ log_tau) {
    const int d = blockIdx.x;
    const int lane = threadIdx.x;

    __shared__ float Kp0[NMID], Kp1[NMID], A0s[NMID], A1s[NMID];
    __shared__ float Sb[NPAD][BW];
    __shared__ float stc[BW];
    __shared__ float gcs[BW];

    const float tau = expf(log_tau[d]);
    const float h = 1.0f / (2.0f * tau * tau);
    const float r255 = expf(-h * 255.0f * 255.0f);
    const float idet = 1.0f / (1.0f - r255 * r255);

    if (lane < BW) gcs[lane] = expf(-h * (float)(lane * lane));

    for (int i = lane; i < NMID; i += 32) {
        float x0 = (float)(i + 1);
        float x1 = (float)(254 - i);
        float k0 = expf(-h * x0 * x0);
        float k1 = expf(-h * x1 * x1);
        Kp0[i] = k0; Kp1[i] = k1;
        float a0 = idet * (k0 - r255 * k1);
        float a1 = idet * (k1 - r255 * k0);
        A0s[i] = a0; A1s[i] = a1;
        g_A0[d][i] = a0; g_A1[d][i] = a1;
    }
    __syncwarp();

    for (int idx = lane; idx < NPAD * BW; idx += 32) {
        int i = idx / BW;
        int c = idx - i * BW;
        float v = 0.0f;
        if (i < NMID) {
            if (c <= i) {
                v = gcs[c] - A0s[i] * Kp0[i - c] - A1s[i] * Kp1[i - c];
                if (c == 0) v += EPSv;
            }
        } else {
            v = (c == 0) ? 1.0f : 0.0f;
        }
        Sb[i][c] = v;
    }
    __syncwarp();

    float W[9][9];
#pragma unroll
    for (int s = 0; s < 9; ++s)
#pragma unroll
        for (int c = 0; c < 9; ++c)
            W[s][c] = Sb[s][c];

    float prod = 1.0f;
    float ld_skip = 0.0f;
    float lprev[9];
#pragma unroll
    for (int c = 0; c < 9; ++c) lprev[c] = -1.0f;
    bool conv = false, jumped = false;
    int j = 0;
    float* __restrict__ Ld = g_Lb[d];

    while (j < NSTEP) {
        if (conv && !jumped && j <= 225) {
#pragma unroll
            for (int c = 0; c < 9; ++c)
                if (lane == c) stc[c] = lprev[c];
            __syncwarp();
            const int skip = JUMPJ - j;
            for (int idx = lane; idx < skip * BW; idx += 32) {
                int jc = j + idx / BW;
                int c  = idx - (idx / BW) * BW;
                int r  = jc + c;
                if (r < NMID)
                    Ld[r * BWP + c] = stc[c];
            }
            __syncwarp();
            ld_skip = (float)skip * logf(lprev[0]);
            j = JUMPJ;
            jumped = true;
        }
#pragma unroll
        for (int s = 0; s < 9; ++s) {
            float x = W[s][0];
            float inv = rsqrtf(x);
            float dg = x * inv;

            float l[9];
            l[0] = dg;
#pragma unroll
            for (int c = 1; c < 9; ++c)
                l[c] = W[(s + c) % 9][c] * inv;

            bool eq = true;
#pragma unroll
            for (int c = 0; c < 9; ++c) eq = eq && (l[c] == lprev[c]);
            if (eq && j >= 12) conv = true;
#pragma unroll
            for (int c = 0; c < 9; ++c) lprev[c] = l[c];

#pragma unroll
            for (int c = 0; c < 9; ++c)
                if (lane == c && j + c < NMID)
                    Ld[(j + c) * BWP + c] = l[c];

#pragma unroll
            for (int r1 = 1; r1 < 9; ++r1)
#pragma unroll
                for (int r2 = 1; r2 <= r1; ++r2)
                    W[(s + r1) % 9][r1 - r2] -= l[r1] * l[r2];

            {
                const float* src = Sb[j + 9];
#pragma unroll
                for (int c = 0; c < 9; ++c)
                    W[s][c] = src[c];
            }

            if (j < NMID) prod *= dg;
            ++j;
        }
    }

    if (lane == 0) g_pld[d] = logf(prod) + ld_skip;
}

// ---------------------------------------------------------------------------
// Apply: cp.async smem pipeline. Block = (d, 32 km-rows), 8 iterations of
// 4-row chunks, 4-stage smem ring, 3 groups in flight. Each thread owns 4
// consecutive t; taps in registers; window read as 3 conflict-free LDS.128
// from front-padded rows (pad zeroed once; taps beyond band are zero).
// ---------------------------------------------------------------------------
__global__ __launch_bounds__(256, 3) void apply_kernel(const float* __restrict__ z,
                                                       const float* __restrict__ sldj,
                                                       float* __restrict__ out,
                                                       int osize) {
    __shared__ float sbuf[NROWBUF * RSTRIDE];

    const int d = blockIdx.x;
    const int chunk = blockIdx.y;          // 0..15, 32 km-rows each
    const int tid = threadIdx.x;
    const int tg = tid & 63;               // t-position group
    const int rs = tid >> 6;               // row slot 0..3
    const int t0 = tg << 2;

    if (d == 0 && chunk == 0 && tid == 0) {
        float s = sldj[0];
        for (int dd = 0; dd < ND; ++dd) s += g_pld[dd];
        out[osize - 1] = s;
    }

    // zero the 8-float front pads of all 16 row buffers (taps outside band are 0,
    // but 0 * garbage-NaN would poison, so pads must be clean)
    if (tid < NROWBUF * 8)
        sbuf[(tid >> 3) * RSTRIDE + (tid & 7)] = 0.0f;

    // per-thread taps (registers)
    float L[4][9];
    float a0[4], a1[4];
#pragma unroll
    for (int u = 0; u < 4; ++u) {
        int i = t0 + u - 1;
        bool valid = (i >= 0) && (i < NMID);
        if (valid) {
            const float4* p = reinterpret_cast<const float4*>(&g_Lb[d][i * BWP]);
            float4 f0 = p[0], f1 = p[1], f2 = p[2];
            L[u][0] = f0.x; L[u][1] = f0.y; L[u][2] = f0.z; L[u][3] = f0.w;
            L[u][4] = f1.x; L[u][5] = f1.y; L[u][6] = f1.z; L[u][7] = f1.w;
            L[u][8] = f2.x;
            a0[u] = g_A0[d][i];
            a1[u] = g_A1[d][i];
        } else {
#pragma unroll
            for (int c = 0; c < 9; ++c) L[u][c] = 0.0f;
            a0[u] = 0.0f; a1[u] = 0.0f;
        }
    }

    // staging addresses: this thread copies 16B of row (chunk*32 + it*4 + rs)
    const int km0 = chunk * 32 + rs;
    const float* __restrict__ zsrc = z + (size_t)(km0 * ND + d) * Tn + (tg << 2);
    const size_t zstep = (size_t)4 * ND * Tn;          // 4 km-rows
    unsigned sdst_base;
    {
        void* p = (void*)&sbuf[0];
        sdst_base = (unsigned)__cvta_generic_to_shared(p);
    }
    const unsigned sdst_off = (rs * RSTRIDE + 8 + (tg << 2)) * 4u;  // bytes within stage

    // prologue: issue 3 groups
#pragma unroll
    for (int p = 0; p < 3; ++p) {
        unsigned dst = sdst_base + ((p & 3) * 4 * RSTRIDE * 4u) + sdst_off;
        const float* src = zsrc + (size_t)p * zstep;
        asm volatile("cp.async.cg.shared.global [%0], [%1], 16;\n" :: "r"(dst), "l"(src));
        asm volatile("cp.async.commit_group;\n" ::: "memory");
    }

    float* __restrict__ orow = out + (size_t)(km0 * ND + d) * Tn + t0;

#pragma unroll
    for (int it = 0; it < 8; ++it) {
        asm volatile("cp.async.wait_group 2;\n" ::: "memory");
        __syncthreads();

        // issue group it+3 (targets stage (it+3)&3 == (it-1)&3, safe post-barrier)
        if (it + 3 < 8) {
            unsigned dst = sdst_base + (((it + 3) & 3) * 4 * RSTRIDE * 4u) + sdst_off;
            const float* src = zsrc + (size_t)(it + 3) * zstep;
            asm volatile("cp.async.cg.shared.global [%0], [%1], 16;\n" :: "r"(dst), "l"(src));
        }
        asm volatile("cp.async.commit_group;\n" ::: "memory");

        // compute from stage it&3, row rs
        const float* rb = &sbuf[((it & 3) * 4 + rs) * RSTRIDE];
        float4 f0 = *reinterpret_cast<const float4*>(rb + t0);      // z[t0-8..t0-5]
        float4 f1 = *reinterpret_cast<const float4*>(rb + t0 + 4);  // z[t0-4..t0-1]
        float4 f2 = *reinterpret_cast<const float4*>(rb + t0 + 8);  // z[t0..t0+3]
        float z0 = rb[8];
        float zE = rb[8 + 255];

        float w[12];
        w[0] = f0.x; w[1] = f0.y; w[2] = f0.z; w[3] = f0.w;
        w[4] = f1.x; w[5] = f1.y; w[6] = f1.z; w[7] = f1.w;
        w[8] = f2.x; w[9] = f2.y; w[10] = f2.z; w[11] = f2.w;

        float v[4];
#pragma unroll
        for (int u = 0; u < 4; ++u) {
            float acc = a0[u] * z0 + a1[u] * zE;
#pragma unroll
            for (int c = 0; c < 9; ++c)
                acc += L[u][c] * w[u - c + 8];
            v[u] = acc;
        }
        if (tg == 0)  v[0] = z0;
        if (tg == 63) v[3] = zE;

        *reinterpret_cast<float4*>(orow + (size_t)it * zstep) = make_float4(v[0], v[1], v[2], v[3]);
    }
}

extern "C" void kernel_launch(void* const* d_in, const int* in_sizes, int n_in,
                              void* d_out, int out_size) {
    const float* z = (const float*)d_in[0];
    const float* sldj = (const float*)d_in[1];
    const float* log_tau = (const float*)d_in[2];
    float* out = (float*)d_out;

    setup_kernel<<<ND, 32>>>(log_tau);
    apply_kernel<<<dim3(ND, 16), 256>>>(z, sldj, out, out_size);
}